// round 14
// baseline (speedup 1.0000x reference)
#include <cuda_runtime.h>
#include <math.h>

#define BATCH 128
#define NPTS  196
#define PDIM  768
#define DIM   384
#define KC    16
#define EE    8
#define NITERS 10
#define NCLS  1000
#define KSPLIT 8
#define ROWS  (BATCH * KC)   // 2048

// ---------------- scratch (device globals; no allocation allowed) ----------------
__device__ float g_patches[BATCH * NPTS * DIM];
__device__ float g_pn[BATCH * NPTS * DIM];
__device__ float g_clusters[ROWS * DIM];
__device__ float g_q[ROWS * DIM];
__device__ float g_kk[ROWS * DIM];
__device__ float g_v[ROWS * DIM];
__device__ float g_mid[ROWS * DIM];
__device__ float g_t1[ROWS * DIM];
__device__ float g_t2[ROWS * DIM];
__device__ float g_c2[ROWS * DIM];
__device__ float g_flat[ROWS * DIM];
__device__ unsigned int g_mask[256];
__device__ float g_cpart[KSPLIT * BATCH * NCLS];

__global__ void nop1_k() {}

// ------- patch GEMM with fused im2col: [25088,768] @ [768,384] + pb --------------
__global__ __launch_bounds__(256, 2) void gemm_patch(const float* __restrict__ x,
                                                     const float* __restrict__ Bw,
                                                     const float* __restrict__ bias) {
    __shared__ float As[16][132];
    __shared__ float Bs[16][132];
    int bm = blockIdx.y * 128, bn = blockIdx.x * 128;
    int tid = threadIdx.x;
    int ty = tid >> 4, tx = tid & 15;

    int kqA = tid & 3;
    int rowA[2];
    size_t baseA[2];
#pragma unroll
    for (int l = 0; l < 2; l++) {
        rowA[l] = (tid >> 2) + l * 64;
        int r = bm + rowA[l];
        int b = r / 196;
        int n = r - b * 196;
        int hp = n / 14, wp = n - hp * 14;
        baseA[l] = ((size_t)(b * 3) * 224 + hp * 16) * 224 + wp * 16;
    }
    int rB0 = tid >> 5;
    int cB = (tid & 31) * 4;

    float4 aReg[2], bReg[2];
#pragma unroll
    for (int l = 0; l < 2; l++) {
        int k = kqA * 4;
        int c = k >> 8, ph = (k >> 4) & 15, pw = k & 15;
        aReg[l] = *(const float4*)&x[baseA[l] + (size_t)c * 50176 + ph * 224 + pw];
        bReg[l] = *(const float4*)&Bw[(size_t)(rB0 + l * 8) * DIM + bn + cB];
    }

    float acc[8][8];
#pragma unroll
    for (int i = 0; i < 8; i++)
#pragma unroll
        for (int j = 0; j < 8; j++) acc[i][j] = 0.f;

    for (int k0 = 0; k0 < PDIM; k0 += 16) {
#pragma unroll
        for (int l = 0; l < 2; l++) {
            As[kqA * 4 + 0][rowA[l]] = aReg[l].x;
            As[kqA * 4 + 1][rowA[l]] = aReg[l].y;
            As[kqA * 4 + 2][rowA[l]] = aReg[l].z;
            As[kqA * 4 + 3][rowA[l]] = aReg[l].w;
            *(float4*)&Bs[rB0 + l * 8][cB] = bReg[l];
        }
        __syncthreads();
        if (k0 + 16 < PDIM) {
            int kn = k0 + 16;
#pragma unroll
            for (int l = 0; l < 2; l++) {
                int k = kn + kqA * 4;
                int c = k >> 8, ph = (k >> 4) & 15, pw = k & 15;
                aReg[l] = *(const float4*)&x[baseA[l] + (size_t)c * 50176 + ph * 224 + pw];
                bReg[l] = *(const float4*)&Bw[(size_t)(kn + rB0 + l * 8) * DIM + bn + cB];
            }
        }
#pragma unroll
        for (int kk = 0; kk < 16; kk++) {
            float4 a0 = *(const float4*)&As[kk][ty * 4];
            float4 a1 = *(const float4*)&As[kk][64 + ty * 4];
            float4 b0 = *(const float4*)&Bs[kk][tx * 4];
            float4 b1 = *(const float4*)&Bs[kk][64 + tx * 4];
            float av[8] = {a0.x, a0.y, a0.z, a0.w, a1.x, a1.y, a1.z, a1.w};
            float bv[8] = {b0.x, b0.y, b0.z, b0.w, b1.x, b1.y, b1.z, b1.w};
#pragma unroll
            for (int i = 0; i < 8; i++)
#pragma unroll
                for (int j = 0; j < 8; j++) acc[i][j] += av[i] * bv[j];
        }
        __syncthreads();
    }

    int col0 = bn + tx * 4, col1 = bn + 64 + tx * 4;
    float4 bi0 = *(const float4*)&bias[col0];
    float4 bi1 = *(const float4*)&bias[col1];
#pragma unroll
    for (int i = 0; i < 8; i++) {
        int rowg = bm + ((i < 4) ? (ty * 4 + i) : (64 + ty * 4 + i - 4));
        float4 o0, o1;
        o0.x = acc[i][0] + bi0.x; o0.y = acc[i][1] + bi0.y;
        o0.z = acc[i][2] + bi0.z; o0.w = acc[i][3] + bi0.w;
        o1.x = acc[i][4] + bi1.x; o1.y = acc[i][5] + bi1.y;
        o1.z = acc[i][6] + bi1.z; o1.w = acc[i][7] + bi1.w;
        *(float4*)&g_patches[(size_t)rowg * DIM + col0] = o0;
        *(float4*)&g_patches[(size_t)rowg * DIM + col1] = o1;
    }
}

// ---------------- LayerNorm per row (384), 128 threads/row; block0 clears mask ----
__global__ void ln_k(const float* __restrict__ gam, const float* __restrict__ bet) {
    int r = blockIdx.x, t = threadIdx.x;
    if (r == 0) { g_mask[t] = 0u; g_mask[t + 128] = 0u; }
    const float* row = g_patches + (size_t)r * DIM;
    float v0 = row[t], v1 = row[t + 128], v2 = row[t + 256];
    float s = v0 + v1 + v2;
    float s2 = v0 * v0 + v1 * v1 + v2 * v2;
#pragma unroll
    for (int o = 16; o > 0; o >>= 1) {
        s += __shfl_xor_sync(0xffffffffu, s, o);
        s2 += __shfl_xor_sync(0xffffffffu, s2, o);
    }
    __shared__ float aa[4], bb[4];
    if ((t & 31) == 0) { aa[t >> 5] = s; bb[t >> 5] = s2; }
    __syncthreads();
    float su = aa[0] + aa[1] + aa[2] + aa[3];
    float sq = bb[0] + bb[1] + bb[2] + bb[3];
    float mu = su * (1.f / 384.f);
    float var = sq * (1.f / 384.f) - mu * mu;
    float rstd = 1.f / sqrtf(var + 1e-5f);
    float* o = g_pn + (size_t)r * DIM;
    o[t]       = (v0 - mu) * rstd * gam[t]       + bet[t];
    o[t + 128] = (v1 - mu) * rstd * gam[t + 128] + bet[t + 128];
    o[t + 256] = (v2 - mu) * rstd * gam[t + 256] + bet[t + 256];
}

// ---------------- k-means: 10 iterations, 1024 threads, one block per batch -------
__global__ __launch_bounds__(1024) void kmeans_k(const float* __restrict__ pos) {
    extern __shared__ float sm[];
    float* centers = sm;
    float* accum   = sm + KC * DIM;
    __shared__ int   asgn[NPTS];
    __shared__ int   scnt[KC];
    __shared__ float csq[KC];
    int b = blockIdx.x, t = threadIdx.x;
    const float* pnb = g_pn + (size_t)b * NPTS * DIM;

    for (int e = t; e < KC * DIM; e += 1024) {
        int k = e / DIM, d = e - k * DIM;
        centers[e] = pnb[(13 * k) * DIM + d];
    }
    __syncthreads();

    for (int iter = 0; iter < NITERS; ++iter) {
        if (t < 512) {   // ||c_k||^2: one warp per center
            int w = t >> 5, lane = t & 31;
            float p = 0.f;
#pragma unroll
            for (int i = 0; i < 12; i++) {
                float cv = centers[w * DIM + lane + 32 * i];
                p += cv * cv;
            }
#pragma unroll
            for (int o = 16; o > 0; o >>= 1) p += __shfl_xor_sync(0xffffffffu, p, o);
            if (lane == 0) csq[w] = p;
        }
        __syncthreads();
        if (t < 784) {   // assignment: 1 thread per (point, quarter-D), 24.5 warps
            int p = t >> 2, q = t & 3;
            unsigned msk = (t < 768) ? 0xffffffffu : 0xffffu;
            int fb = q * 24;
            float acc[KC];
#pragma unroll
            for (int k = 0; k < KC; k++) acc[k] = 0.f;
            const float4* c4 = (const float4*)centers;
            const float4* vp = (const float4*)pnb + p * 96 + fb;
            for (int i = 0; i < 24; i += 4) {
                float4 v0 = vp[i + 0];
                float4 v1 = vp[i + 1];
                float4 v2 = vp[i + 2];
                float4 v3 = vp[i + 3];
#pragma unroll
                for (int k = 0; k < KC; k++) {
                    const float4* cp = c4 + k * 96 + fb + i;
                    float4 c0 = cp[0], c1 = cp[1], c2 = cp[2], c3 = cp[3];
                    float s = acc[k];
                    s += v0.x * c0.x + v0.y * c0.y + v0.z * c0.z + v0.w * c0.w;
                    s += v1.x * c1.x + v1.y * c1.y + v1.z * c1.z + v1.w * c1.w;
                    s += v2.x * c2.x + v2.y * c2.y + v2.z * c2.z + v2.w * c2.w;
                    s += v3.x * c3.x + v3.y * c3.y + v3.z * c3.z + v3.w * c3.w;
                    acc[k] = s;
                }
            }
#pragma unroll
            for (int k = 0; k < KC; k++) {
                float r = acc[k];
                r += __shfl_xor_sync(msk, r, 1);
                r += __shfl_xor_sync(msk, r, 2);
                acc[k] = r;
            }
            if (q == 0) {
                float best = csq[0] - 2.f * acc[0];
                int bi = 0;
#pragma unroll
                for (int k = 1; k < KC; k++) {
                    float scv = csq[k] - 2.f * acc[k];
                    if (scv < best) { best = scv; bi = k; }
                }
                asgn[p] = bi;
            }
        }
        if (t < KC) scnt[t] = 0;
        __syncthreads();
        {   // accumulation: 2 warps per cluster (half-D each), register accumulators
            int w = t >> 5, lane = t & 31;
            int kc = w >> 1, hh = w & 1;
            int dof = hh * 192 + lane;
            float ac[6];
#pragma unroll
            for (int r = 0; r < 6; r++) ac[r] = 0.f;
            for (int n0 = 0; n0 < NPTS; n0 += 4) {
                int a0 = asgn[n0 + 0], a1 = asgn[n0 + 1];
                int a2 = asgn[n0 + 2], a3 = asgn[n0 + 3];
                if (a0 == kc) {
                    const float* rp = pnb + (n0 + 0) * DIM + dof;
#pragma unroll
                    for (int r = 0; r < 6; r++) ac[r] += rp[r * 32];
                }
                if (a1 == kc) {
                    const float* rp = pnb + (n0 + 1) * DIM + dof;
#pragma unroll
                    for (int r = 0; r < 6; r++) ac[r] += rp[r * 32];
                }
                if (a2 == kc) {
                    const float* rp = pnb + (n0 + 2) * DIM + dof;
#pragma unroll
                    for (int r = 0; r < 6; r++) ac[r] += rp[r * 32];
                }
                if (a3 == kc) {
                    const float* rp = pnb + (n0 + 3) * DIM + dof;
#pragma unroll
                    for (int r = 0; r < 6; r++) ac[r] += rp[r * 32];
                }
            }
#pragma unroll
            for (int r = 0; r < 6; r++) accum[kc * DIM + dof + r * 32] = ac[r];
        }
        if (t < NPTS) atomicAdd(&scnt[asgn[t]], 1);
        __syncthreads();
        float newc[KC];
        if (t < DIM) {
#pragma unroll
            for (int k = 0; k < KC; k++) {
                int c = scnt[k];
                newc[k] = (c > 0) ? (accum[k * DIM + t] / (float)c) : centers[k * DIM + t];
            }
        }
        __syncthreads();
        if (t < DIM) {
#pragma unroll
            for (int k = 0; k < KC; k++) centers[k * DIM + t] = newc[k];
        }
        __syncthreads();
    }
    for (int e = t; e < KC * DIM; e += 1024)
        g_clusters[(size_t)b * KC * DIM + e] = centers[e] + pos[e];
}

// ------- 64x128-tile GEMM body, 128 threads, 8x8 microtile (A rows broadcast) -----
__device__ __forceinline__ void gemm64x128(const float* __restrict__ A,
                                           const float* __restrict__ W,
                                           const float* __restrict__ bias,
                                           float* __restrict__ C,
                                           int bm, int wcol, int gelu) {
    __shared__ float As[16][68];
    __shared__ float Bs[16][132];
    int tid = threadIdx.x;
    int ty = tid >> 4, tx = tid & 15;

    int rowA = tid >> 2;
    int kqA = (tid & 3) * 4;
    int rB = tid >> 5;
    int cB = (tid & 31) * 4;

    float4 aReg[2], bReg[4];
#pragma unroll
    for (int l = 0; l < 2; l++)
        aReg[l] = *(const float4*)&A[(size_t)(bm + rowA + l * 32) * DIM + kqA];
#pragma unroll
    for (int l = 0; l < 4; l++)
        bReg[l] = *(const float4*)&W[(size_t)(rB + l * 4) * DIM + wcol + cB];

    float acc[8][8];
#pragma unroll
    for (int i = 0; i < 8; i++)
#pragma unroll
        for (int j = 0; j < 8; j++) acc[i][j] = 0.f;

    for (int k0 = 0; k0 < DIM; k0 += 16) {
#pragma unroll
        for (int l = 0; l < 2; l++) {
            As[kqA + 0][rowA + l * 32] = aReg[l].x;
            As[kqA + 1][rowA + l * 32] = aReg[l].y;
            As[kqA + 2][rowA + l * 32] = aReg[l].z;
            As[kqA + 3][rowA + l * 32] = aReg[l].w;
        }
#pragma unroll
        for (int l = 0; l < 4; l++)
            *(float4*)&Bs[rB + l * 4][cB] = bReg[l];
        __syncthreads();
        if (k0 + 16 < DIM) {
#pragma unroll
            for (int l = 0; l < 2; l++)
                aReg[l] = *(const float4*)&A[(size_t)(bm + rowA + l * 32) * DIM + k0 + 16 + kqA];
#pragma unroll
            for (int l = 0; l < 4; l++)
                bReg[l] = *(const float4*)&W[(size_t)(k0 + 16 + rB + l * 4) * DIM + wcol + cB];
        }
#pragma unroll
        for (int kk = 0; kk < 16; kk++) {
            float4 a0 = *(const float4*)&As[kk][ty * 4];
            float4 a1 = *(const float4*)&As[kk][32 + ty * 4];
            float4 b0 = *(const float4*)&Bs[kk][tx * 4];
            float4 b1 = *(const float4*)&Bs[kk][64 + tx * 4];
            float av[8] = {a0.x, a0.y, a0.z, a0.w, a1.x, a1.y, a1.z, a1.w};
            float bv[8] = {b0.x, b0.y, b0.z, b0.w, b1.x, b1.y, b1.z, b1.w};
#pragma unroll
            for (int i = 0; i < 8; i++)
#pragma unroll
                for (int j = 0; j < 8; j++) acc[i][j] += av[i] * bv[j];
        }
        __syncthreads();
    }

    float4 bi0 = *(const float4*)&bias[wcol + tx * 4];
    float4 bi1 = *(const float4*)&bias[wcol + 64 + tx * 4];
    float bb0[4] = {bi0.x, bi0.y, bi0.z, bi0.w};
    float bb1[4] = {bi1.x, bi1.y, bi1.z, bi1.w};
#pragma unroll
    for (int i = 0; i < 8; i++) {
        int rowg = bm + (i >> 2) * 32 + ty * 4 + (i & 3);
        float v[8];
#pragma unroll
        for (int j = 0; j < 4; j++) {
            float u0 = acc[i][j] + bb0[j];
            float u1 = acc[i][4 + j] + bb1[j];
            if (gelu) {
                u0 = 0.5f * u0 * (1.f + erff(u0 * 0.70710678118654752f));
                u1 = 0.5f * u1 * (1.f + erff(u1 * 0.70710678118654752f));
            }
            v[j] = u0; v[4 + j] = u1;
        }
        float4 o0 = {v[0], v[1], v[2], v[3]};
        float4 o1 = {v[4], v[5], v[6], v[7]};
        *(float4*)&C[(size_t)rowg * DIM + wcol + tx * 4] = o0;
        *(float4*)&C[(size_t)rowg * DIM + wcol + 64 + tx * 4] = o1;
    }
}

// QKV: grid (9, 32); col blocks 0-2 -> Q, 3-5 -> K, 6-8 -> V
__global__ __launch_bounds__(128, 4) void qkv_k(
    const float* __restrict__ qw, const float* __restrict__ qb,
    const float* __restrict__ kw, const float* __restrict__ kb,
    const float* __restrict__ vw, const float* __restrict__ vb) {
    int nb = blockIdx.x;
    const float* W; const float* bias; float* out;
    if (nb < 3)      { W = qw; bias = qb; out = g_q; }
    else if (nb < 6) { W = kw; bias = kb; out = g_kk; nb -= 3; }
    else             { W = vw; bias = vb; out = g_v;  nb -= 6; }
    gemm64x128(g_clusters, W, bias, out, blockIdx.y * 64, nb * 128, 0);
}

// MLP chain: mode 0: g_mid@nw->g_t1; 1: g_t1@m1w(+gelu)->g_t2; 2: g_t2@m2w->g_c2
__global__ __launch_bounds__(128, 4) void mlp_k(const float* __restrict__ W,
                                                const float* __restrict__ bias,
                                                int mode) {
    const float* A = (mode == 0) ? g_mid : (mode == 1) ? g_t1 : g_t2;
    float* C = (mode == 0) ? g_t1 : (mode == 1) ? g_t2 : g_c2;
    gemm64x128(A, W, bias, C, blockIdx.y * 64, blockIdx.x * 128, (mode == 1) ? 1 : 0);
}

// ---------------- attention middle: scores/softmax/AV/hypergraph/L@AV -------------
__global__ __launch_bounds__(384) void attn_mid_k(const float* __restrict__ ew,
                                                  const float* __restrict__ eb) {
    extern __shared__ float sm[];
    float* Qs = sm;            // 16x384 (reused as AV)
    float* Ks = sm + 6144;
    float* Vs = sm + 12288;
    __shared__ float ews[DIM * EE];
    __shared__ float sc[256];
    __shared__ float hpart[KC * EE * 3];
    __shared__ float hsc[KC * EE];
    __shared__ float rDd[EE];
    __shared__ float Lm[EE * EE];
    int b = blockIdx.x, t = threadIdx.x;
    size_t base = (size_t)b * KC * DIM;

#pragma unroll
    for (int k = 0; k < KC; k++) {
        Qs[k * DIM + t] = g_q[base + k * DIM + t];
        Ks[k * DIM + t] = g_kk[base + k * DIM + t];
        Vs[k * DIM + t] = g_v[base + k * DIM + t];
    }
#pragma unroll
    for (int i = 0; i < 8; i++) ews[t + i * 384] = ew[t + i * 384];
    __syncthreads();
    if (t < 256) {
        int q = t >> 4, kk = t & 15;
        const float4* Q4 = (const float4*)Qs;
        const float4* K4 = (const float4*)Ks;
        float s = 0.f;
        for (int i = 0; i < 96; i++) {
            float4 a = Q4[q * 96 + i];
            float4 c = K4[kk * 96 + i];
            s += a.x * c.x + a.y * c.y + a.z * c.z + a.w * c.w;
        }
        sc[t] = s * 0.05103103630798288f;
    }
    __syncthreads();
    if (t < KC) {
        float m = -1e30f;
#pragma unroll
        for (int k = 0; k < KC; k++) m = fmaxf(m, sc[t * 16 + k]);
        float e[KC], su = 0.f;
#pragma unroll
        for (int k = 0; k < KC; k++) { e[k] = expf(sc[t * 16 + k] - m); su += e[k]; }
        float inv = 1.f / su;
#pragma unroll
        for (int k = 0; k < KC; k++) sc[t * 16 + k] = e[k] * inv;
    }
    __syncthreads();
    {
        float nv[KC];
#pragma unroll
        for (int q = 0; q < KC; q++) {
            float s = 0.f;
#pragma unroll
            for (int k = 0; k < KC; k++) s += sc[q * 16 + k] * Vs[k * DIM + t];
            nv[q] = s;
        }
        __syncthreads();
#pragma unroll
        for (int q = 0; q < KC; q++) Qs[q * DIM + t] = nv[q];   // AV
    }
    __syncthreads();
    {   // hyperedge logits: 3 threads per (k,e) output, 128-d slices
        int k = t / 24;
        int rem = t - k * 24;
        int e = rem / 3, r = rem - e * 3;
        int d0 = r * 128;
        float s = 0.f;
        for (int d = 0; d < 128; d++)
            s += Qs[k * DIM + d0 + d] * ews[(d0 + d) * EE + e];
        hpart[t] = s;
    }
    __syncthreads();
    if (t < 128) {
        int k = t >> 3, e = t & 7;
        int p0 = (k * 8 + e) * 3;
        hsc[k * EE + e] = hpart[p0] + hpart[p0 + 1] + hpart[p0 + 2] + eb[e];
    }
    __syncthreads();
    if (t < EE) {
        float m = -1e30f;
#pragma unroll
        for (int k = 0; k < KC; k++) m = fmaxf(m, hsc[k * EE + t]);
        float ex[KC], su = 0.f;
#pragma unroll
        for (int k = 0; k < KC; k++) { ex[k] = expf(hsc[k * EE + t] - m); su += ex[k]; }
        float inv = 1.f / su, dd = 0.f;
#pragma unroll
        for (int k = 0; k < KC; k++) { float h = ex[k] * inv; hsc[k * EE + t] = h; dd += h; }
        rDd[t] = 1.f / sqrtf(dd);
    }
    __syncthreads();
    if (t < 64) {
        int e = t >> 3, f = t & 7;
        float s = 0.f;
#pragma unroll
        for (int k = 0; k < KC; k++) s += hsc[k * EE + e] * hsc[k * EE + f];
        Lm[t] = ((e == f) ? 1.f : 0.f) - rDd[e] * s;
    }
    __syncthreads();
    {
        float lv[EE];
#pragma unroll
        for (int i = 0; i < EE; i++) {
            float s = 0.f;
#pragma unroll
            for (int f = 0; f < EE; f++) s += Lm[i * EE + f] * Qs[f * DIM + t];
            lv[i] = s;
        }
#pragma unroll
        for (int i = 0; i < EE; i++) g_mid[base + i * DIM + t] = lv[i];
#pragma unroll
        for (int i = EE; i < KC; i++) g_mid[base + i * DIM + t] = 0.f;
    }
}

// ---------------- cosine-similarity mask over batch ----------------
__global__ __launch_bounds__(384) void mask_k() {
    __shared__ float A[KC * DIM];
    __shared__ float pna[256];
    __shared__ float nrm[KC];
    int b = blockIdx.x, t = threadIdx.x;
    size_t base = (size_t)b * KC * DIM;
#pragma unroll
    for (int k = 0; k < KC; k++) A[k * DIM + t] = g_c2[base + k * DIM + t];
    __syncthreads();
    if (t < 256) {
        int k = t >> 4, l = t & 15;
        float s = 0.f;
#pragma unroll
        for (int i = 0; i < 24; i++) {
            float v = A[k * DIM + l + 16 * i];
            s += v * v;
        }
        pna[t] = s;
    }
    __syncthreads();
    if (t < KC) {
        float s = 0.f;
#pragma unroll
        for (int l = 0; l < 16; l++) s += pna[t * 16 + l];
        nrm[t] = fmaxf(sqrtf(s), 1e-12f);
    }
    __syncthreads();
    if (t < 120) {
        int i = 0, rem = t, cnt = 15;
        while (rem >= cnt) { rem -= cnt; cnt--; i++; }
        int j = i + 1 + rem;
        float s = 0.f;
        for (int d = 0; d < DIM; d++) s += A[i * DIM + d] * A[j * DIM + d];
        if (s / (nrm[i] * nrm[j]) > 0.9f) atomicOr(&g_mask[i * 16 + j], 1u);
    }
}

// ---------------- sequential merge + gated fusion (block = batch) ----------------
__global__ __launch_bounds__(384) void merge_k(const float* __restrict__ fbw,
                                               const float* __restrict__ fbb,
                                               const float* __restrict__ fgw,
                                               const float* __restrict__ fgb) {
    __shared__ unsigned int msk[256];
    __shared__ float gsh[DIM];
    __shared__ float wsum[12];
    __shared__ float gate_s;
    int b = blockIdx.x, t = threadIdx.x;
    if (t < 256) msk[t] = g_mask[t];
    float c[KC];
#pragma unroll
    for (int k = 0; k < KC; k++) c[k] = g_c2[(size_t)b * KC * DIM + k * DIM + t];
    __syncthreads();
#pragma unroll
    for (int i = 0; i < KC; i++)
#pragma unroll
        for (int j = i + 1; j < KC; j++)
            if (msk[i * 16 + j]) {
                float m = (c[i] + c[j]) * 0.5f;
                c[i] = m;
                c[j] = m;
            }
    float g = 0.f;
#pragma unroll
    for (int k = 0; k < KC; k++) g += c[k];
    g *= (1.f / 16.f);
    gsh[t] = g;
    float p = g * fgw[t];
#pragma unroll
    for (int o = 16; o > 0; o >>= 1) p += __shfl_xor_sync(0xffffffffu, p, o);
    if ((t & 31) == 0) wsum[t >> 5] = p;
    __syncthreads();
    if (t == 0) {
        float s = 0.f;
#pragma unroll
        for (int i = 0; i < 12; i++) s += wsum[i];
        gate_s = 1.f / (1.f + expf(-(s + fgb[0])));
    }
    __syncthreads();
    float gate = gate_s;
    float acc = 0.f;
    for (int d = 0; d < DIM; d++) acc += gsh[d] * fbw[d * DIM + t];
    float fb = acc + fbb[t];
#pragma unroll
    for (int k = 0; k < KC; k++)
        g_flat[(size_t)b * KC * DIM + k * DIM + t] = c[k] + fb * gate;
}

// ---------------- classifier: [128,6144] @ [6144,1000], split-K ----------------
__global__ __launch_bounds__(256) void cls_k(const float* __restrict__ cw) {
    __shared__ float As[16][132];
    __shared__ float Bs[16][68];
    int bn = blockIdx.x * 64;
    int kz = blockIdx.z;
    int kbase = kz * (KC * DIM / KSPLIT);
    int tid = threadIdx.x;
    int ty = tid >> 4, tx = tid & 15;
    float acc[8][4];
#pragma unroll
    for (int i = 0; i < 8; i++)
#pragma unroll
        for (int j = 0; j < 4; j++) acc[i][j] = 0.f;

    for (int k0 = kbase; k0 < kbase + 768; k0 += 16) {
#pragma unroll
        for (int l = 0; l < 2; l++) {
            int s = tid + l * 256;
            int row = s >> 2, kq = s & 3;
            float4 av = *(const float4*)&g_flat[(size_t)row * (KC * DIM) + k0 + kq * 4];
            As[kq * 4 + 0][row] = av.x;
            As[kq * 4 + 1][row] = av.y;
            As[kq * 4 + 2][row] = av.z;
            As[kq * 4 + 3][row] = av.w;
        }
#pragma unroll
        for (int j = 0; j < 4; j++) {
            int idx = tid * 4 + j;
            int row = idx >> 6, cc = idx & 63;
            int n = bn + cc;
            Bs[row][cc] = (n < NCLS) ? cw[(size_t)(k0 + row) * NCLS + n] : 0.f;
        }
        __syncthreads();
#pragma unroll
        for (int kk = 0; kk < 16; kk++) {
            float4 a0 = *(const float4*)&As[kk][ty * 8];
            float4 a1 = *(const float4*)&As[kk][ty * 8 + 4];
            float4 bb = *(const float4*)&Bs[kk][tx * 4];
            float av[8] = {a0.x, a0.y, a0.z, a0.w, a1.x, a1.y, a1.z, a1.w};
            float bv[4] = {bb.x, bb.y, bb.z, bb.w};
#pragma unroll
            for (int i = 0; i < 8; i++)
#pragma unroll
                for (int j = 0; j < 4; j++) acc[i][j] += av[i] * bv[j];
        }
        __syncthreads();
    }
    float* part = g_cpart + (size_t)kz * BATCH * NCLS;
#pragma unroll
    for (int i = 0; i < 8; i++)
#pragma unroll
        for (int j = 0; j < 4; j++) {
            int n = bn + tx * 4 + j;
            if (n < NCLS) part[(ty * 8 + i) * NCLS + n] = acc[i][j];
        }
}

__global__ void finout_k(const float* __restrict__ cb, float* __restrict__ out) {
    int idx = blockIdx.x * 256 + threadIdx.x;
    if (idx >= BATCH * NCLS) return;
    int n = idx % NCLS;
    float s = cb[n];
#pragma unroll
    for (int z = 0; z < KSPLIT; z++) s += g_cpart[(size_t)z * BATCH * NCLS + idx];
    out[idx] = s;
}

extern "C" void kernel_launch(void* const* d_in, const int* in_sizes, int n_in,
                              void* d_out, int out_size) {
    const float* x    = (const float*)d_in[0];
    const float* pw   = (const float*)d_in[1];
    const float* pb   = (const float*)d_in[2];
    const float* ln_g = (const float*)d_in[3];
    const float* ln_b = (const float*)d_in[4];
    const float* pos  = (const float*)d_in[5];
    const float* qw   = (const float*)d_in[6];
    const float* qb   = (const float*)d_in[7];
    const float* kw   = (const float*)d_in[8];
    const float* kb   = (const float*)d_in[9];
    const float* vw   = (const float*)d_in[10];
    const float* vb   = (const float*)d_in[11];
    const float* ew   = (const float*)d_in[12];
    const float* eb   = (const float*)d_in[13];
    const float* nw   = (const float*)d_in[14];
    const float* nb   = (const float*)d_in[15];
    const float* m1w  = (const float*)d_in[16];
    const float* m1b  = (const float*)d_in[17];
    const float* m2w  = (const float*)d_in[18];
    const float* m2b  = (const float*)d_in[19];
    const float* fbw  = (const float*)d_in[20];
    const float* fbb  = (const float*)d_in[21];
    const float* fgw  = (const float*)d_in[22];
    const float* fgb  = (const float*)d_in[23];
    const float* cw   = (const float*)d_in[24];
    const float* cb   = (const float*)d_in[25];
    float* out = (float*)d_out;

    cudaFuncSetAttribute(kmeans_k,   cudaFuncAttributeMaxDynamicSharedMemorySize, 49152);
    cudaFuncSetAttribute(attn_mid_k, cudaFuncAttributeMaxDynamicSharedMemorySize, 73728);

    // launch order keeps kmeans_k at slot 4 (the ncu capture window) to verify delta
    gemm_patch<<<dim3(3, 196), 256>>>(x, pw, pb);
    ln_k<<<BATCH * NPTS, 128>>>(ln_g, ln_b);
    nop1_k<<<1, 32>>>();
    kmeans_k<<<BATCH, 1024, 49152>>>(pos);
    qkv_k<<<dim3(9, 32), 128>>>(qw, qb, kw, kb, vw, vb);
    attn_mid_k<<<BATCH, 384, 73728>>>(ew, eb);
    mlp_k<<<dim3(3, 32), 128>>>(nw, nb, 0);
    mlp_k<<<dim3(3, 32), 128>>>(m1w, m1b, 1);
    mlp_k<<<dim3(3, 32), 128>>>(m2w, m2b, 2);
    mask_k<<<BATCH, 384>>>();
    merge_k<<<BATCH, 384>>>(fbw, fbb, fgw, fgb);
    cls_k<<<dim3(16, 1, KSPLIT), 256>>>(cw);
    finout_k<<<(BATCH * NCLS + 255) / 256, 256>>>(cb, out);
}

// round 15
// speedup vs baseline: 1.2925x; 1.2925x over previous
#include <cuda_runtime.h>
#include <math.h>

#define BATCH 128
#define NPTS  196
#define PDIM  768
#define DIM   384
#define KC    16
#define EE    8
#define NITERS 10
#define NCLS  1000
#define KSPLIT 8
#define ROWS  (BATCH * KC)   // 2048

// ---------------- scratch (device globals; no allocation allowed) ----------------
__device__ float g_patches[BATCH * NPTS * DIM];
__device__ float g_pn[BATCH * NPTS * DIM];
__device__ float g_cent[BATCH * KC * DIM];
__device__ int   g_asgn[BATCH * NPTS];
__device__ float g_clusters[ROWS * DIM];
__device__ float g_q[ROWS * DIM];
__device__ float g_kk[ROWS * DIM];
__device__ float g_v[ROWS * DIM];
__device__ float g_mid[ROWS * DIM];
__device__ float g_t1[ROWS * DIM];
__device__ float g_t2[ROWS * DIM];
__device__ float g_c2[ROWS * DIM];
__device__ float g_flat[ROWS * DIM];
__device__ unsigned int g_mask[256];
__device__ float g_cpart[KSPLIT * BATCH * NCLS];

// ------- patch GEMM with fused im2col: [25088,768] @ [768,384] + pb --------------
__global__ __launch_bounds__(256, 2) void gemm_patch(const float* __restrict__ x,
                                                     const float* __restrict__ Bw,
                                                     const float* __restrict__ bias) {
    __shared__ float As[16][132];
    __shared__ float Bs[16][132];
    int bm = blockIdx.y * 128, bn = blockIdx.x * 128;
    int tid = threadIdx.x;
    int ty = tid >> 4, tx = tid & 15;

    int kqA = tid & 3;
    int rowA[2];
    size_t baseA[2];
#pragma unroll
    for (int l = 0; l < 2; l++) {
        rowA[l] = (tid >> 2) + l * 64;
        int r = bm + rowA[l];
        int b = r / 196;
        int n = r - b * 196;
        int hp = n / 14, wp = n - hp * 14;
        baseA[l] = ((size_t)(b * 3) * 224 + hp * 16) * 224 + wp * 16;
    }
    int rB0 = tid >> 5;
    int cB = (tid & 31) * 4;

    float4 aReg[2], bReg[2];
#pragma unroll
    for (int l = 0; l < 2; l++) {
        int k = kqA * 4;
        int c = k >> 8, ph = (k >> 4) & 15, pw = k & 15;
        aReg[l] = *(const float4*)&x[baseA[l] + (size_t)c * 50176 + ph * 224 + pw];
        bReg[l] = *(const float4*)&Bw[(size_t)(rB0 + l * 8) * DIM + bn + cB];
    }

    float acc[8][8];
#pragma unroll
    for (int i = 0; i < 8; i++)
#pragma unroll
        for (int j = 0; j < 8; j++) acc[i][j] = 0.f;

    for (int k0 = 0; k0 < PDIM; k0 += 16) {
#pragma unroll
        for (int l = 0; l < 2; l++) {
            As[kqA * 4 + 0][rowA[l]] = aReg[l].x;
            As[kqA * 4 + 1][rowA[l]] = aReg[l].y;
            As[kqA * 4 + 2][rowA[l]] = aReg[l].z;
            As[kqA * 4 + 3][rowA[l]] = aReg[l].w;
            *(float4*)&Bs[rB0 + l * 8][cB] = bReg[l];
        }
        __syncthreads();
        if (k0 + 16 < PDIM) {
            int kn = k0 + 16;
#pragma unroll
            for (int l = 0; l < 2; l++) {
                int k = kn + kqA * 4;
                int c = k >> 8, ph = (k >> 4) & 15, pw = k & 15;
                aReg[l] = *(const float4*)&x[baseA[l] + (size_t)c * 50176 + ph * 224 + pw];
                bReg[l] = *(const float4*)&Bw[(size_t)(kn + rB0 + l * 8) * DIM + bn + cB];
            }
        }
#pragma unroll
        for (int kk = 0; kk < 16; kk++) {
            float4 a0 = *(const float4*)&As[kk][ty * 4];
            float4 a1 = *(const float4*)&As[kk][64 + ty * 4];
            float4 b0 = *(const float4*)&Bs[kk][tx * 4];
            float4 b1 = *(const float4*)&Bs[kk][64 + tx * 4];
            float av[8] = {a0.x, a0.y, a0.z, a0.w, a1.x, a1.y, a1.z, a1.w};
            float bv[8] = {b0.x, b0.y, b0.z, b0.w, b1.x, b1.y, b1.z, b1.w};
#pragma unroll
            for (int i = 0; i < 8; i++)
#pragma unroll
                for (int j = 0; j < 8; j++) acc[i][j] += av[i] * bv[j];
        }
        __syncthreads();
    }

    int col0 = bn + tx * 4, col1 = bn + 64 + tx * 4;
    float4 bi0 = *(const float4*)&bias[col0];
    float4 bi1 = *(const float4*)&bias[col1];
#pragma unroll
    for (int i = 0; i < 8; i++) {
        int rowg = bm + ((i < 4) ? (ty * 4 + i) : (64 + ty * 4 + i - 4));
        float4 o0, o1;
        o0.x = acc[i][0] + bi0.x; o0.y = acc[i][1] + bi0.y;
        o0.z = acc[i][2] + bi0.z; o0.w = acc[i][3] + bi0.w;
        o1.x = acc[i][4] + bi1.x; o1.y = acc[i][5] + bi1.y;
        o1.z = acc[i][6] + bi1.z; o1.w = acc[i][7] + bi1.w;
        *(float4*)&g_patches[(size_t)rowg * DIM + col0] = o0;
        *(float4*)&g_patches[(size_t)rowg * DIM + col1] = o1;
    }
}

// ---------------- LayerNorm per row (384), 128 threads/row; block0 clears mask ----
__global__ void ln_k(const float* __restrict__ gam, const float* __restrict__ bet) {
    int r = blockIdx.x, t = threadIdx.x;
    if (r == 0) { g_mask[t] = 0u; g_mask[t + 128] = 0u; }
    const float* row = g_patches + (size_t)r * DIM;
    float v0 = row[t], v1 = row[t + 128], v2 = row[t + 256];
    float s = v0 + v1 + v2;
    float s2 = v0 * v0 + v1 * v1 + v2 * v2;
#pragma unroll
    for (int o = 16; o > 0; o >>= 1) {
        s += __shfl_xor_sync(0xffffffffu, s, o);
        s2 += __shfl_xor_sync(0xffffffffu, s2, o);
    }
    __shared__ float aa[4], bb[4];
    if ((t & 31) == 0) { aa[t >> 5] = s; bb[t >> 5] = s2; }
    __syncthreads();
    float su = aa[0] + aa[1] + aa[2] + aa[3];
    float sq = bb[0] + bb[1] + bb[2] + bb[3];
    float mu = su * (1.f / 384.f);
    float var = sq * (1.f / 384.f) - mu * mu;
    float rstd = 1.f / sqrtf(var + 1e-5f);
    float* o = g_pn + (size_t)r * DIM;
    o[t]       = (v0 - mu) * rstd * gam[t]       + bet[t];
    o[t + 128] = (v1 - mu) * rstd * gam[t + 128] + bet[t + 128];
    o[t + 256] = (v2 - mu) * rstd * gam[t + 256] + bet[t + 256];
}

// ---------------- k-means split kernels ----------------
__global__ void init_cent_k() {
    int b = blockIdx.x, t = threadIdx.x;  // 384 threads
    const float* pnb = g_pn + (size_t)b * NPTS * DIM;
    float* cd = g_cent + (size_t)b * KC * DIM;
#pragma unroll
    for (int k = 0; k < KC; k++)
        cd[k * DIM + t] = pnb[(13 * k) * DIM + t];
}

// assignment: grid (2, BATCH), 256 threads; 2 threads per point (half-D each)
__global__ void assign_k() {
    __shared__ float centers[KC * DIM];
    __shared__ float csq[KC];
    int y = blockIdx.x, b = blockIdx.y, t = threadIdx.x;
    const float* cent = g_cent + (size_t)b * KC * DIM;
    for (int e = t; e < KC * DIM; e += 256) centers[e] = cent[e];
    __syncthreads();
    {   // csq: 8 warps, 2 centers each
        int w = t >> 5, lane = t & 31;
        for (int kk = w; kk < KC; kk += 8) {
            float p = 0.f;
#pragma unroll
            for (int i = 0; i < 12; i++) {
                float cv = centers[kk * DIM + lane + 32 * i];
                p += cv * cv;
            }
#pragma unroll
            for (int o = 16; o > 0; o >>= 1) p += __shfl_xor_sync(0xffffffffu, p, o);
            if (lane == 0) csq[kk] = p;
        }
    }
    __syncthreads();
    int p = y * 128 + (t >> 1);
    int h = t & 1;
    if (p < NPTS) {
        int warpFirstP = y * 128 + ((t & ~31) >> 1);
        int act = (NPTS - warpFirstP) * 2;
        if (act > 32) act = 32;
        unsigned msk = (act >= 32) ? 0xffffffffu : ((1u << act) - 1u);
        float acc[KC];
#pragma unroll
        for (int k = 0; k < KC; k++) acc[k] = 0.f;
        int fb = h * 48;
        const float4* c4 = (const float4*)centers;
        const float4* vp = (const float4*)(g_pn + (size_t)b * NPTS * DIM) + p * 96 + fb;
        for (int i = 0; i < 48; i += 4) {
            float4 v0 = vp[i + 0];
            float4 v1 = vp[i + 1];
            float4 v2 = vp[i + 2];
            float4 v3 = vp[i + 3];
#pragma unroll
            for (int k = 0; k < KC; k++) {
                const float4* cp = c4 + k * 96 + fb + i;
                float4 c0 = cp[0], c1 = cp[1], c2 = cp[2], c3 = cp[3];
                float s = acc[k];
                s += v0.x * c0.x + v0.y * c0.y + v0.z * c0.z + v0.w * c0.w;
                s += v1.x * c1.x + v1.y * c1.y + v1.z * c1.z + v1.w * c1.w;
                s += v2.x * c2.x + v2.y * c2.y + v2.z * c2.z + v2.w * c2.w;
                s += v3.x * c3.x + v3.y * c3.y + v3.z * c3.z + v3.w * c3.w;
                acc[k] = s;
            }
        }
#pragma unroll
        for (int k = 0; k < KC; k++) acc[k] += __shfl_xor_sync(msk, acc[k], 1);
        if (h == 0) {
            float best = csq[0] - 2.f * acc[0];
            int bi = 0;
#pragma unroll
            for (int k = 1; k < KC; k++) {
                float scv = csq[k] - 2.f * acc[k];
                if (scv < best) { best = scv; bi = k; }
            }
            g_asgn[b * NPTS + p] = bi;
        }
    }
}

// update: grid (KC, BATCH), 384 threads; thread = d-column of cluster k
__global__ void update_k() {
    __shared__ int asgn[NPTS];
    int k = blockIdx.x, b = blockIdx.y, t = threadIdx.x;
    const int* ga = g_asgn + b * NPTS;
    if (t < NPTS) asgn[t] = ga[t];
    __syncthreads();
    const float* pnb = g_pn + (size_t)b * NPTS * DIM;
    float ac = 0.f;
    int cnt = 0;
    for (int n0 = 0; n0 < NPTS; n0 += 4) {
        int a0 = asgn[n0 + 0], a1 = asgn[n0 + 1];
        int a2 = asgn[n0 + 2], a3 = asgn[n0 + 3];
        if (a0 == k) { ac += pnb[(n0 + 0) * DIM + t]; cnt++; }
        if (a1 == k) { ac += pnb[(n0 + 1) * DIM + t]; cnt++; }
        if (a2 == k) { ac += pnb[(n0 + 2) * DIM + t]; cnt++; }
        if (a3 == k) { ac += pnb[(n0 + 3) * DIM + t]; cnt++; }
    }
    float* cd = g_cent + (size_t)b * KC * DIM + k * DIM + t;
    float oldv = *cd;
    *cd = (cnt > 0) ? (ac / (float)cnt) : oldv;
}

__global__ void finalize_k(const float* __restrict__ pos) {
    int b = blockIdx.x, t = threadIdx.x;  // 384 threads
    const float* cd = g_cent + (size_t)b * KC * DIM;
    float* cl = g_clusters + (size_t)b * KC * DIM;
#pragma unroll
    for (int k = 0; k < KC; k++)
        cl[k * DIM + t] = cd[k * DIM + t] + pos[k * DIM + t];
}

// ------- 64x128-tile GEMM body, 128 threads, 8x8 microtile (A rows broadcast) -----
__device__ __forceinline__ void gemm64x128(const float* __restrict__ A,
                                           const float* __restrict__ W,
                                           const float* __restrict__ bias,
                                           float* __restrict__ C,
                                           int bm, int wcol, int gelu) {
    __shared__ float As[16][68];
    __shared__ float Bs[16][132];
    int tid = threadIdx.x;
    int ty = tid >> 4, tx = tid & 15;

    int rowA = tid >> 2;
    int kqA = (tid & 3) * 4;
    int rB = tid >> 5;
    int cB = (tid & 31) * 4;

    float4 aReg[2], bReg[4];
#pragma unroll
    for (int l = 0; l < 2; l++)
        aReg[l] = *(const float4*)&A[(size_t)(bm + rowA + l * 32) * DIM + kqA];
#pragma unroll
    for (int l = 0; l < 4; l++)
        bReg[l] = *(const float4*)&W[(size_t)(rB + l * 4) * DIM + wcol + cB];

    float acc[8][8];
#pragma unroll
    for (int i = 0; i < 8; i++)
#pragma unroll
        for (int j = 0; j < 8; j++) acc[i][j] = 0.f;

    for (int k0 = 0; k0 < DIM; k0 += 16) {
#pragma unroll
        for (int l = 0; l < 2; l++) {
            As[kqA + 0][rowA + l * 32] = aReg[l].x;
            As[kqA + 1][rowA + l * 32] = aReg[l].y;
            As[kqA + 2][rowA + l * 32] = aReg[l].z;
            As[kqA + 3][rowA + l * 32] = aReg[l].w;
        }
#pragma unroll
        for (int l = 0; l < 4; l++)
            *(float4*)&Bs[rB + l * 4][cB] = bReg[l];
        __syncthreads();
        if (k0 + 16 < DIM) {
#pragma unroll
            for (int l = 0; l < 2; l++)
                aReg[l] = *(const float4*)&A[(size_t)(bm + rowA + l * 32) * DIM + k0 + 16 + kqA];
#pragma unroll
            for (int l = 0; l < 4; l++)
                bReg[l] = *(const float4*)&W[(size_t)(k0 + 16 + rB + l * 4) * DIM + wcol + cB];
        }
#pragma unroll
        for (int kk = 0; kk < 16; kk++) {
            float4 a0 = *(const float4*)&As[kk][ty * 4];
            float4 a1 = *(const float4*)&As[kk][32 + ty * 4];
            float4 b0 = *(const float4*)&Bs[kk][tx * 4];
            float4 b1 = *(const float4*)&Bs[kk][64 + tx * 4];
            float av[8] = {a0.x, a0.y, a0.z, a0.w, a1.x, a1.y, a1.z, a1.w};
            float bv[8] = {b0.x, b0.y, b0.z, b0.w, b1.x, b1.y, b1.z, b1.w};
#pragma unroll
            for (int i = 0; i < 8; i++)
#pragma unroll
                for (int j = 0; j < 8; j++) acc[i][j] += av[i] * bv[j];
        }
        __syncthreads();
    }

    float4 bi0 = *(const float4*)&bias[wcol + tx * 4];
    float4 bi1 = *(const float4*)&bias[wcol + 64 + tx * 4];
    float bb0[4] = {bi0.x, bi0.y, bi0.z, bi0.w};
    float bb1[4] = {bi1.x, bi1.y, bi1.z, bi1.w};
#pragma unroll
    for (int i = 0; i < 8; i++) {
        int rowg = bm + (i >> 2) * 32 + ty * 4 + (i & 3);
        float v[8];
#pragma unroll
        for (int j = 0; j < 4; j++) {
            float u0 = acc[i][j] + bb0[j];
            float u1 = acc[i][4 + j] + bb1[j];
            if (gelu) {
                u0 = 0.5f * u0 * (1.f + erff(u0 * 0.70710678118654752f));
                u1 = 0.5f * u1 * (1.f + erff(u1 * 0.70710678118654752f));
            }
            v[j] = u0; v[4 + j] = u1;
        }
        float4 o0 = {v[0], v[1], v[2], v[3]};
        float4 o1 = {v[4], v[5], v[6], v[7]};
        *(float4*)&C[(size_t)rowg * DIM + wcol + tx * 4] = o0;
        *(float4*)&C[(size_t)rowg * DIM + wcol + 64 + tx * 4] = o1;
    }
}

// QKV: grid (9, 32); col blocks 0-2 -> Q, 3-5 -> K, 6-8 -> V
__global__ __launch_bounds__(128, 4) void qkv_k(
    const float* __restrict__ qw, const float* __restrict__ qb,
    const float* __restrict__ kw, const float* __restrict__ kb,
    const float* __restrict__ vw, const float* __restrict__ vb) {
    int nb = blockIdx.x;
    const float* W; const float* bias; float* out;
    if (nb < 3)      { W = qw; bias = qb; out = g_q; }
    else if (nb < 6) { W = kw; bias = kb; out = g_kk; nb -= 3; }
    else             { W = vw; bias = vb; out = g_v;  nb -= 6; }
    gemm64x128(g_clusters, W, bias, out, blockIdx.y * 64, nb * 128, 0);
}

// MLP chain: mode 0: g_mid@nw->g_t1; 1: g_t1@m1w(+gelu)->g_t2; 2: g_t2@m2w->g_c2
__global__ __launch_bounds__(128, 4) void mlp_k(const float* __restrict__ W,
                                                const float* __restrict__ bias,
                                                int mode) {
    const float* A = (mode == 0) ? g_mid : (mode == 1) ? g_t1 : g_t2;
    float* C = (mode == 0) ? g_t1 : (mode == 1) ? g_t2 : g_c2;
    gemm64x128(A, W, bias, C, blockIdx.y * 64, blockIdx.x * 128, (mode == 1) ? 1 : 0);
}

// ---------------- attention middle: scores/softmax/AV/hypergraph/L@AV -------------
__global__ __launch_bounds__(384) void attn_mid_k(const float* __restrict__ ew,
                                                  const float* __restrict__ eb) {
    extern __shared__ float sm[];
    float* Qs = sm;            // 16x384 (reused as AV)
    float* Ks = sm + 6144;
    float* Vs = sm + 12288;
    __shared__ float ews[DIM * EE];
    __shared__ float sc[256];
    __shared__ float hpart[KC * EE * 3];
    __shared__ float hsc[KC * EE];
    __shared__ float rDd[EE];
    __shared__ float Lm[EE * EE];
    int b = blockIdx.x, t = threadIdx.x;
    size_t base = (size_t)b * KC * DIM;

#pragma unroll
    for (int k = 0; k < KC; k++) {
        Qs[k * DIM + t] = g_q[base + k * DIM + t];
        Ks[k * DIM + t] = g_kk[base + k * DIM + t];
        Vs[k * DIM + t] = g_v[base + k * DIM + t];
    }
#pragma unroll
    for (int i = 0; i < 8; i++) ews[t + i * 384] = ew[t + i * 384];
    __syncthreads();
    if (t < 256) {
        int q = t >> 4, kk = t & 15;
        const float4* Q4 = (const float4*)Qs;
        const float4* K4 = (const float4*)Ks;
        float s = 0.f;
        for (int i = 0; i < 96; i++) {
            float4 a = Q4[q * 96 + i];
            float4 c = K4[kk * 96 + i];
            s += a.x * c.x + a.y * c.y + a.z * c.z + a.w * c.w;
        }
        sc[t] = s * 0.05103103630798288f;
    }
    __syncthreads();
    if (t < KC) {
        float m = -1e30f;
#pragma unroll
        for (int k = 0; k < KC; k++) m = fmaxf(m, sc[t * 16 + k]);
        float e[KC], su = 0.f;
#pragma unroll
        for (int k = 0; k < KC; k++) { e[k] = expf(sc[t * 16 + k] - m); su += e[k]; }
        float inv = 1.f / su;
#pragma unroll
        for (int k = 0; k < KC; k++) sc[t * 16 + k] = e[k] * inv;
    }
    __syncthreads();
    {
        float nv[KC];
#pragma unroll
        for (int q = 0; q < KC; q++) {
            float s = 0.f;
#pragma unroll
            for (int k = 0; k < KC; k++) s += sc[q * 16 + k] * Vs[k * DIM + t];
            nv[q] = s;
        }
        __syncthreads();
#pragma unroll
        for (int q = 0; q < KC; q++) Qs[q * DIM + t] = nv[q];   // AV
    }
    __syncthreads();
    {   // hyperedge logits: 3 threads per (k,e) output, 128-d slices
        int k = t / 24;
        int rem = t - k * 24;
        int e = rem / 3, r = rem - e * 3;
        int d0 = r * 128;
        float s = 0.f;
        for (int d = 0; d < 128; d++)
            s += Qs[k * DIM + d0 + d] * ews[(d0 + d) * EE + e];
        hpart[t] = s;
    }
    __syncthreads();
    if (t < 128) {
        int k = t >> 3, e = t & 7;
        int p0 = (k * 8 + e) * 3;
        hsc[k * EE + e] = hpart[p0] + hpart[p0 + 1] + hpart[p0 + 2] + eb[e];
    }
    __syncthreads();
    if (t < EE) {
        float m = -1e30f;
#pragma unroll
        for (int k = 0; k < KC; k++) m = fmaxf(m, hsc[k * EE + t]);
        float ex[KC], su = 0.f;
#pragma unroll
        for (int k = 0; k < KC; k++) { ex[k] = expf(hsc[k * EE + t] - m); su += ex[k]; }
        float inv = 1.f / su, dd = 0.f;
#pragma unroll
        for (int k = 0; k < KC; k++) { float h = ex[k] * inv; hsc[k * EE + t] = h; dd += h; }
        rDd[t] = 1.f / sqrtf(dd);
    }
    __syncthreads();
    if (t < 64) {
        int e = t >> 3, f = t & 7;
        float s = 0.f;
#pragma unroll
        for (int k = 0; k < KC; k++) s += hsc[k * EE + e] * hsc[k * EE + f];
        Lm[t] = ((e == f) ? 1.f : 0.f) - rDd[e] * s;
    }
    __syncthreads();
    {
        float lv[EE];
#pragma unroll
        for (int i = 0; i < EE; i++) {
            float s = 0.f;
#pragma unroll
            for (int f = 0; f < EE; f++) s += Lm[i * EE + f] * Qs[f * DIM + t];
            lv[i] = s;
        }
#pragma unroll
        for (int i = 0; i < EE; i++) g_mid[base + i * DIM + t] = lv[i];
#pragma unroll
        for (int i = EE; i < KC; i++) g_mid[base + i * DIM + t] = 0.f;
    }
}

// ---------------- cosine-similarity mask over batch ----------------
__global__ __launch_bounds__(384) void mask_k() {
    __shared__ float A[KC * DIM];
    __shared__ float pna[256];
    __shared__ float nrm[KC];
    int b = blockIdx.x, t = threadIdx.x;
    size_t base = (size_t)b * KC * DIM;
#pragma unroll
    for (int k = 0; k < KC; k++) A[k * DIM + t] = g_c2[base + k * DIM + t];
    __syncthreads();
    if (t < 256) {
        int k = t >> 4, l = t & 15;
        float s = 0.f;
#pragma unroll
        for (int i = 0; i < 24; i++) {
            float v = A[k * DIM + l + 16 * i];
            s += v * v;
        }
        pna[t] = s;
    }
    __syncthreads();
    if (t < KC) {
        float s = 0.f;
#pragma unroll
        for (int l = 0; l < 16; l++) s += pna[t * 16 + l];
        nrm[t] = fmaxf(sqrtf(s), 1e-12f);
    }
    __syncthreads();
    if (t < 120) {
        int i = 0, rem = t, cnt = 15;
        while (rem >= cnt) { rem -= cnt; cnt--; i++; }
        int j = i + 1 + rem;
        float s = 0.f;
        for (int d = 0; d < DIM; d++) s += A[i * DIM + d] * A[j * DIM + d];
        if (s / (nrm[i] * nrm[j]) > 0.9f) atomicOr(&g_mask[i * 16 + j], 1u);
    }
}

// ---------------- sequential merge + gated fusion (block = batch) ----------------
__global__ __launch_bounds__(384) void merge_k(const float* __restrict__ fbw,
                                               const float* __restrict__ fbb,
                                               const float* __restrict__ fgw,
                                               const float* __restrict__ fgb) {
    __shared__ unsigned int msk[256];
    __shared__ float gsh[DIM];
    __shared__ float wsum[12];
    __shared__ float gate_s;
    int b = blockIdx.x, t = threadIdx.x;
    if (t < 256) msk[t] = g_mask[t];
    float c[KC];
#pragma unroll
    for (int k = 0; k < KC; k++) c[k] = g_c2[(size_t)b * KC * DIM + k * DIM + t];
    __syncthreads();
#pragma unroll
    for (int i = 0; i < KC; i++)
#pragma unroll
        for (int j = i + 1; j < KC; j++)
            if (msk[i * 16 + j]) {
                float m = (c[i] + c[j]) * 0.5f;
                c[i] = m;
                c[j] = m;
            }
    float g = 0.f;
#pragma unroll
    for (int k = 0; k < KC; k++) g += c[k];
    g *= (1.f / 16.f);
    gsh[t] = g;
    float p = g * fgw[t];
#pragma unroll
    for (int o = 16; o > 0; o >>= 1) p += __shfl_xor_sync(0xffffffffu, p, o);
    if ((t & 31) == 0) wsum[t >> 5] = p;
    __syncthreads();
    if (t == 0) {
        float s = 0.f;
#pragma unroll
        for (int i = 0; i < 12; i++) s += wsum[i];
        gate_s = 1.f / (1.f + expf(-(s + fgb[0])));
    }
    __syncthreads();
    float gate = gate_s;
    float acc = 0.f;
    for (int d = 0; d < DIM; d++) acc += gsh[d] * fbw[d * DIM + t];
    float fb = acc + fbb[t];
#pragma unroll
    for (int k = 0; k < KC; k++)
        g_flat[(size_t)b * KC * DIM + k * DIM + t] = c[k] + fb * gate;
}

// ---------------- classifier: [128,6144] @ [6144,1000], split-K ----------------
__global__ __launch_bounds__(256) void cls_k(const float* __restrict__ cw) {
    __shared__ float As[16][132];
    __shared__ float Bs[16][68];
    int bn = blockIdx.x * 64;
    int kz = blockIdx.z;
    int kbase = kz * (KC * DIM / KSPLIT);
    int tid = threadIdx.x;
    int ty = tid >> 4, tx = tid & 15;
    float acc[8][4];
#pragma unroll
    for (int i = 0; i < 8; i++)
#pragma unroll
        for (int j = 0; j < 4; j++) acc[i][j] = 0.f;

    for (int k0 = kbase; k0 < kbase + 768; k0 += 16) {
#pragma unroll
        for (int l = 0; l < 2; l++) {
            int s = tid + l * 256;
            int row = s >> 2, kq = s & 3;
            float4 av = *(const float4*)&g_flat[(size_t)row * (KC * DIM) + k0 + kq * 4];
            As[kq * 4 + 0][row] = av.x;
            As[kq * 4 + 1][row] = av.y;
            As[kq * 4 + 2][row] = av.z;
            As[kq * 4 + 3][row] = av.w;
        }
#pragma unroll
        for (int j = 0; j < 4; j++) {
            int idx = tid * 4 + j;
            int row = idx >> 6, cc = idx & 63;
            int n = bn + cc;
            Bs[row][cc] = (n < NCLS) ? cw[(size_t)(k0 + row) * NCLS + n] : 0.f;
        }
        __syncthreads();
#pragma unroll
        for (int kk = 0; kk < 16; kk++) {
            float4 a0 = *(const float4*)&As[kk][ty * 8];
            float4 a1 = *(const float4*)&As[kk][ty * 8 + 4];
            float4 bb = *(const float4*)&Bs[kk][tx * 4];
            float av[8] = {a0.x, a0.y, a0.z, a0.w, a1.x, a1.y, a1.z, a1.w};
            float bv[4] = {bb.x, bb.y, bb.z, bb.w};
#pragma unroll
            for (int i = 0; i < 8; i++)
#pragma unroll
                for (int j = 0; j < 4; j++) acc[i][j] += av[i] * bv[j];
        }
        __syncthreads();
    }
    float* part = g_cpart + (size_t)kz * BATCH * NCLS;
#pragma unroll
    for (int i = 0; i < 8; i++)
#pragma unroll
        for (int j = 0; j < 4; j++) {
            int n = bn + tx * 4 + j;
            if (n < NCLS) part[(ty * 8 + i) * NCLS + n] = acc[i][j];
        }
}

__global__ void finout_k(const float* __restrict__ cb, float* __restrict__ out) {
    int idx = blockIdx.x * 256 + threadIdx.x;
    if (idx >= BATCH * NCLS) return;
    int n = idx % NCLS;
    float s = cb[n];
#pragma unroll
    for (int z = 0; z < KSPLIT; z++) s += g_cpart[(size_t)z * BATCH * NCLS + idx];
    out[idx] = s;
}

extern "C" void kernel_launch(void* const* d_in, const int* in_sizes, int n_in,
                              void* d_out, int out_size) {
    const float* x    = (const float*)d_in[0];
    const float* pw   = (const float*)d_in[1];
    const float* pb   = (const float*)d_in[2];
    const float* ln_g = (const float*)d_in[3];
    const float* ln_b = (const float*)d_in[4];
    const float* pos  = (const float*)d_in[5];
    const float* qw   = (const float*)d_in[6];
    const float* qb   = (const float*)d_in[7];
    const float* kw   = (const float*)d_in[8];
    const float* kb   = (const float*)d_in[9];
    const float* vw   = (const float*)d_in[10];
    const float* vb   = (const float*)d_in[11];
    const float* ew   = (const float*)d_in[12];
    const float* eb   = (const float*)d_in[13];
    const float* nw   = (const float*)d_in[14];
    const float* nb   = (const float*)d_in[15];
    const float* m1w  = (const float*)d_in[16];
    const float* m1b  = (const float*)d_in[17];
    const float* m2w  = (const float*)d_in[18];
    const float* m2b  = (const float*)d_in[19];
    const float* fbw  = (const float*)d_in[20];
    const float* fbb  = (const float*)d_in[21];
    const float* fgw  = (const float*)d_in[22];
    const float* fgb  = (const float*)d_in[23];
    const float* cw   = (const float*)d_in[24];
    const float* cb   = (const float*)d_in[25];
    float* out = (float*)d_out;

    cudaFuncSetAttribute(attn_mid_k, cudaFuncAttributeMaxDynamicSharedMemorySize, 73728);

    gemm_patch<<<dim3(3, 196), 256>>>(x, pw, pb);
    ln_k<<<BATCH * NPTS, 128>>>(ln_g, ln_b);
    init_cent_k<<<BATCH, 384>>>();
    for (int it = 0; it < NITERS; ++it) {
        assign_k<<<dim3(2, BATCH), 256>>>();
        update_k<<<dim3(KC, BATCH), 384>>>();
    }
    finalize_k<<<BATCH, 384>>>(pos);
    qkv_k<<<dim3(9, 32), 128>>>(qw, qb, kw, kb, vw, vb);
    attn_mid_k<<<BATCH, 384, 73728>>>(ew, eb);
    mlp_k<<<dim3(3, 32), 128>>>(nw, nb, 0);
    mlp_k<<<dim3(3, 32), 128>>>(m1w, m1b, 1);
    mlp_k<<<dim3(3, 32), 128>>>(m2w, m2b, 2);
    mask_k<<<BATCH, 384>>>();
    merge_k<<<BATCH, 384>>>(fbw, fbb, fgw, fgb);
    cls_k<<<dim3(16, 1, KSPLIT), 256>>>(cw);
    finout_k<<<(BATCH * NCLS + 255) / 256, 256>>>(cb, out);
}

// round 16
// speedup vs baseline: 1.6678x; 1.2903x over previous
#include <cuda_runtime.h>
#include <math.h>

#define BATCH 128
#define NPTS  196
#define PDIM  768
#define DIM   384
#define KC    16
#define EE    8
#define NITERS 10
#define NCLS  1000
#define KSPLIT 8
#define ROWS  (BATCH * KC)   // 2048

// ---------------- scratch (device globals; no allocation allowed) ----------------
__device__ float g_patches[BATCH * NPTS * DIM];
__device__ float g_pn[BATCH * NPTS * DIM];
__device__ float g_clusters[ROWS * DIM];
__device__ float g_q[ROWS * DIM];
__device__ float g_kk[ROWS * DIM];
__device__ float g_v[ROWS * DIM];
__device__ float g_mid[ROWS * DIM];
__device__ float g_t1[ROWS * DIM];
__device__ float g_t2[ROWS * DIM];
__device__ float g_c2[ROWS * DIM];
__device__ float g_flat[ROWS * DIM];
__device__ unsigned int g_mask[256];
__device__ float g_cpart[KSPLIT * BATCH * NCLS];

__global__ void nop1_k() {}
__global__ void nop2_k() {}
__global__ void nop3_k() {}

// ------- patch GEMM with fused im2col: [25088,768] @ [768,384] + pb --------------
// BM=128, BN=128, BK=16, 256 threads, 8x8 microtile, DOUBLE-BUFFERED smem
__global__ __launch_bounds__(256, 2) void gemm_patch(const float* __restrict__ x,
                                                     const float* __restrict__ Bw,
                                                     const float* __restrict__ bias) {
    __shared__ float As[2][16][132];
    __shared__ float Bs[2][16][132];
    int bm = blockIdx.y * 128, bn = blockIdx.x * 128;
    int tid = threadIdx.x;
    int ty = tid >> 4, tx = tid & 15;

    int kqA = tid & 3;
    int rowA[2];
    size_t baseA[2];
#pragma unroll
    for (int l = 0; l < 2; l++) {
        rowA[l] = (tid >> 2) + l * 64;
        int r = bm + rowA[l];
        int b = r / 196;
        int n = r - b * 196;
        int hp = n / 14, wp = n - hp * 14;
        baseA[l] = ((size_t)(b * 3) * 224 + hp * 16) * 224 + wp * 16;
    }
    int rB0 = tid >> 5;
    int cB = (tid & 31) * 4;

    float4 aReg[2], bReg[2];
#pragma unroll
    for (int l = 0; l < 2; l++) {
        int k = kqA * 4;
        int c = k >> 8, ph = (k >> 4) & 15, pw = k & 15;
        aReg[l] = *(const float4*)&x[baseA[l] + (size_t)c * 50176 + ph * 224 + pw];
        bReg[l] = *(const float4*)&Bw[(size_t)(rB0 + l * 8) * DIM + bn + cB];
    }

    float acc[8][8];
#pragma unroll
    for (int i = 0; i < 8; i++)
#pragma unroll
        for (int j = 0; j < 8; j++) acc[i][j] = 0.f;

    // prologue: fill buffer 0
#pragma unroll
    for (int l = 0; l < 2; l++) {
        As[0][kqA * 4 + 0][rowA[l]] = aReg[l].x;
        As[0][kqA * 4 + 1][rowA[l]] = aReg[l].y;
        As[0][kqA * 4 + 2][rowA[l]] = aReg[l].z;
        As[0][kqA * 4 + 3][rowA[l]] = aReg[l].w;
        *(float4*)&Bs[0][rB0 + l * 8][cB] = bReg[l];
    }
    __syncthreads();

    int cur = 0;
    for (int k0 = 0; k0 < PDIM; k0 += 16) {
        bool hasNext = (k0 + 16 < PDIM);
        if (hasNext) {   // issue next tile's global loads before compute
            int kn = k0 + 16;
#pragma unroll
            for (int l = 0; l < 2; l++) {
                int k = kn + kqA * 4;
                int c = k >> 8, ph = (k >> 4) & 15, pw = k & 15;
                aReg[l] = *(const float4*)&x[baseA[l] + (size_t)c * 50176 + ph * 224 + pw];
                bReg[l] = *(const float4*)&Bw[(size_t)(kn + rB0 + l * 8) * DIM + bn + cB];
            }
        }
#pragma unroll
        for (int kk = 0; kk < 16; kk++) {
            float4 a0 = *(const float4*)&As[cur][kk][ty * 4];
            float4 a1 = *(const float4*)&As[cur][kk][64 + ty * 4];
            float4 b0 = *(const float4*)&Bs[cur][kk][tx * 4];
            float4 b1 = *(const float4*)&Bs[cur][kk][64 + tx * 4];
            float av[8] = {a0.x, a0.y, a0.z, a0.w, a1.x, a1.y, a1.z, a1.w};
            float bv[8] = {b0.x, b0.y, b0.z, b0.w, b1.x, b1.y, b1.z, b1.w};
#pragma unroll
            for (int i = 0; i < 8; i++)
#pragma unroll
                for (int j = 0; j < 8; j++) acc[i][j] += av[i] * bv[j];
        }
        if (hasNext) {   // store next tile to the other buffer, single barrier
            int nxt = cur ^ 1;
#pragma unroll
            for (int l = 0; l < 2; l++) {
                As[nxt][kqA * 4 + 0][rowA[l]] = aReg[l].x;
                As[nxt][kqA * 4 + 1][rowA[l]] = aReg[l].y;
                As[nxt][kqA * 4 + 2][rowA[l]] = aReg[l].z;
                As[nxt][kqA * 4 + 3][rowA[l]] = aReg[l].w;
                *(float4*)&Bs[nxt][rB0 + l * 8][cB] = bReg[l];
            }
            __syncthreads();
            cur = nxt;
        }
    }

    int col0 = bn + tx * 4, col1 = bn + 64 + tx * 4;
    float4 bi0 = *(const float4*)&bias[col0];
    float4 bi1 = *(const float4*)&bias[col1];
#pragma unroll
    for (int i = 0; i < 8; i++) {
        int rowg = bm + ((i < 4) ? (ty * 4 + i) : (64 + ty * 4 + i - 4));
        float4 o0, o1;
        o0.x = acc[i][0] + bi0.x; o0.y = acc[i][1] + bi0.y;
        o0.z = acc[i][2] + bi0.z; o0.w = acc[i][3] + bi0.w;
        o1.x = acc[i][4] + bi1.x; o1.y = acc[i][5] + bi1.y;
        o1.z = acc[i][6] + bi1.z; o1.w = acc[i][7] + bi1.w;
        *(float4*)&g_patches[(size_t)rowg * DIM + col0] = o0;
        *(float4*)&g_patches[(size_t)rowg * DIM + col1] = o1;
    }
}

// ---------------- LayerNorm per row (384), 128 threads/row; block0 clears mask ----
__global__ void ln_k(const float* __restrict__ gam, const float* __restrict__ bet) {
    int r = blockIdx.x, t = threadIdx.x;
    if (r == 0) { g_mask[t] = 0u; g_mask[t + 128] = 0u; }
    const float* row = g_patches + (size_t)r * DIM;
    float v0 = row[t], v1 = row[t + 128], v2 = row[t + 256];
    float s = v0 + v1 + v2;
    float s2 = v0 * v0 + v1 * v1 + v2 * v2;
#pragma unroll
    for (int o = 16; o > 0; o >>= 1) {
        s += __shfl_xor_sync(0xffffffffu, s, o);
        s2 += __shfl_xor_sync(0xffffffffu, s2, o);
    }
    __shared__ float aa[4], bb[4];
    if ((t & 31) == 0) { aa[t >> 5] = s; bb[t >> 5] = s2; }
    __syncthreads();
    float su = aa[0] + aa[1] + aa[2] + aa[3];
    float sq = bb[0] + bb[1] + bb[2] + bb[3];
    float mu = su * (1.f / 384.f);
    float var = sq * (1.f / 384.f) - mu * mu;
    float rstd = 1.f / sqrtf(var + 1e-5f);
    float* o = g_pn + (size_t)r * DIM;
    o[t]       = (v0 - mu) * rstd * gam[t]       + bet[t];
    o[t + 128] = (v1 - mu) * rstd * gam[t + 128] + bet[t + 128];
    o[t + 256] = (v2 - mu) * rstd * gam[t + 256] + bet[t + 256];
}

// ---------------- k-means: 10 iterations, one block per batch (R13 proven) --------
__global__ __launch_bounds__(512) void kmeans_k(const float* __restrict__ pos) {
    extern __shared__ float sm[];
    float* centers = sm;
    float* accum   = sm + KC * DIM;
    __shared__ int   asgn[NPTS];
    __shared__ int   scnt[KC];
    __shared__ float csq[KC];
    int b = blockIdx.x, t = threadIdx.x;
    const float* pnb = g_pn + (size_t)b * NPTS * DIM;

    for (int e = t; e < KC * DIM; e += 512) {
        int k = e / DIM, d = e - k * DIM;
        centers[e] = pnb[(13 * k) * DIM + d];
    }
    __syncthreads();

    for (int iter = 0; iter < NITERS; ++iter) {
        {   // ||c_k||^2: one warp per center
            int w = t >> 5, lane = t & 31;
            float p = 0.f;
#pragma unroll
            for (int i = 0; i < 12; i++) {
                float cv = centers[w * DIM + lane + 32 * i];
                p += cv * cv;
            }
#pragma unroll
            for (int o = 16; o > 0; o >>= 1) p += __shfl_xor_sync(0xffffffffu, p, o);
            if (lane == 0) csq[w] = p;
        }
        __syncthreads();
        if (t < 392) {   // assignment: 2 threads/point (half-D), 4x unroll + prefetch
            int p = t >> 1, h = t & 1;
            int fb = h * 48;
            unsigned msk = (t < 384) ? 0xffffffffu : 0xffu;
            float acc[KC];
#pragma unroll
            for (int k = 0; k < KC; k++) acc[k] = 0.f;
            const float4* c4 = (const float4*)centers;
            const float4* vp = (const float4*)pnb + p * 96 + fb;
            float4 vb0 = vp[0], vb1 = vp[1], vb2 = vp[2], vb3 = vp[3];
            for (int i = 0; i < 48; i += 4) {
                int nx = (i + 4 < 48) ? (i + 4) : i;
                float4 vn0 = vp[nx + 0];
                float4 vn1 = vp[nx + 1];
                float4 vn2 = vp[nx + 2];
                float4 vn3 = vp[nx + 3];
#pragma unroll
                for (int k = 0; k < KC; k++) {
                    const float4* cp = c4 + k * 96 + fb + i;
                    float4 c0 = cp[0], c1 = cp[1], c2 = cp[2], c3 = cp[3];
                    float s = acc[k];
                    s += vb0.x * c0.x + vb0.y * c0.y + vb0.z * c0.z + vb0.w * c0.w;
                    s += vb1.x * c1.x + vb1.y * c1.y + vb1.z * c1.z + vb1.w * c1.w;
                    s += vb2.x * c2.x + vb2.y * c2.y + vb2.z * c2.z + vb2.w * c2.w;
                    s += vb3.x * c3.x + vb3.y * c3.y + vb3.z * c3.z + vb3.w * c3.w;
                    acc[k] = s;
                }
                vb0 = vn0; vb1 = vn1; vb2 = vn2; vb3 = vn3;
            }
#pragma unroll
            for (int k = 0; k < KC; k++) acc[k] += __shfl_xor_sync(msk, acc[k], 1);
            if (h == 0) {
                float best = csq[0] - 2.f * acc[0];
                int bi = 0;
#pragma unroll
                for (int k = 1; k < KC; k++) {
                    float scv = csq[k] - 2.f * acc[k];
                    if (scv < best) { best = scv; bi = k; }
                }
                asgn[p] = bi;
            }
        }
        if (t < KC) scnt[t] = 0;
        __syncthreads();
        {   // warp-per-cluster register accumulation
            int w = t >> 5, lane = t & 31;
            float ac[12];
#pragma unroll
            for (int r = 0; r < 12; r++) ac[r] = 0.f;
            for (int n0 = 0; n0 < NPTS; n0 += 4) {
                int a0 = asgn[n0 + 0], a1 = asgn[n0 + 1];
                int a2 = asgn[n0 + 2], a3 = asgn[n0 + 3];
                if (a0 == w) {
                    const float* rp = pnb + (n0 + 0) * DIM + lane;
#pragma unroll
                    for (int r = 0; r < 12; r++) ac[r] += rp[r * 32];
                }
                if (a1 == w) {
                    const float* rp = pnb + (n0 + 1) * DIM + lane;
#pragma unroll
                    for (int r = 0; r < 12; r++) ac[r] += rp[r * 32];
                }
                if (a2 == w) {
                    const float* rp = pnb + (n0 + 2) * DIM + lane;
#pragma unroll
                    for (int r = 0; r < 12; r++) ac[r] += rp[r * 32];
                }
                if (a3 == w) {
                    const float* rp = pnb + (n0 + 3) * DIM + lane;
#pragma unroll
                    for (int r = 0; r < 12; r++) ac[r] += rp[r * 32];
                }
            }
#pragma unroll
            for (int r = 0; r < 12; r++) accum[w * DIM + r * 32 + lane] = ac[r];
        }
        if (t < NPTS) atomicAdd(&scnt[asgn[t]], 1);
        __syncthreads();
        float newc[KC];
        if (t < DIM) {
#pragma unroll
            for (int k = 0; k < KC; k++) {
                int c = scnt[k];
                newc[k] = (c > 0) ? (accum[k * DIM + t] / (float)c) : centers[k * DIM + t];
            }
        }
        __syncthreads();
        if (t < DIM) {
#pragma unroll
            for (int k = 0; k < KC; k++) centers[k * DIM + t] = newc[k];
        }
        __syncthreads();
    }
    for (int e = t; e < KC * DIM; e += 512)
        g_clusters[(size_t)b * KC * DIM + e] = centers[e] + pos[e];
}

// ------- 64x128-tile GEMM body, 128 threads, 8x8 microtile (A rows broadcast) -----
__device__ __forceinline__ void gemm64x128(const float* __restrict__ A,
                                           const float* __restrict__ W,
                                           const float* __restrict__ bias,
                                           float* __restrict__ C,
                                           int bm, int wcol, int gelu) {
    __shared__ float As[16][68];
    __shared__ float Bs[16][132];
    int tid = threadIdx.x;
    int ty = tid >> 4, tx = tid & 15;

    int rowA = tid >> 2;
    int kqA = (tid & 3) * 4;
    int rB = tid >> 5;
    int cB = (tid & 31) * 4;

    float4 aReg[2], bReg[4];
#pragma unroll
    for (int l = 0; l < 2; l++)
        aReg[l] = *(const float4*)&A[(size_t)(bm + rowA + l * 32) * DIM + kqA];
#pragma unroll
    for (int l = 0; l < 4; l++)
        bReg[l] = *(const float4*)&W[(size_t)(rB + l * 4) * DIM + wcol + cB];

    float acc[8][8];
#pragma unroll
    for (int i = 0; i < 8; i++)
#pragma unroll
        for (int j = 0; j < 8; j++) acc[i][j] = 0.f;

    for (int k0 = 0; k0 < DIM; k0 += 16) {
#pragma unroll
        for (int l = 0; l < 2; l++) {
            As[kqA + 0][rowA + l * 32] = aReg[l].x;
            As[kqA + 1][rowA + l * 32] = aReg[l].y;
            As[kqA + 2][rowA + l * 32] = aReg[l].z;
            As[kqA + 3][rowA + l * 32] = aReg[l].w;
        }
#pragma unroll
        for (int l = 0; l < 4; l++)
            *(float4*)&Bs[rB + l * 4][cB] = bReg[l];
        __syncthreads();
        if (k0 + 16 < DIM) {
#pragma unroll
            for (int l = 0; l < 2; l++)
                aReg[l] = *(const float4*)&A[(size_t)(bm + rowA + l * 32) * DIM + k0 + 16 + kqA];
#pragma unroll
            for (int l = 0; l < 4; l++)
                bReg[l] = *(const float4*)&W[(size_t)(k0 + 16 + rB + l * 4) * DIM + wcol + cB];
        }
#pragma unroll
        for (int kk = 0; kk < 16; kk++) {
            float4 a0 = *(const float4*)&As[kk][ty * 4];
            float4 a1 = *(const float4*)&As[kk][32 + ty * 4];
            float4 b0 = *(const float4*)&Bs[kk][tx * 4];
            float4 b1 = *(const float4*)&Bs[kk][64 + tx * 4];
            float av[8] = {a0.x, a0.y, a0.z, a0.w, a1.x, a1.y, a1.z, a1.w};
            float bv[8] = {b0.x, b0.y, b0.z, b0.w, b1.x, b1.y, b1.z, b1.w};
#pragma unroll
            for (int i = 0; i < 8; i++)
#pragma unroll
                for (int j = 0; j < 8; j++) acc[i][j] += av[i] * bv[j];
        }
        __syncthreads();
    }

    float4 bi0 = *(const float4*)&bias[wcol + tx * 4];
    float4 bi1 = *(const float4*)&bias[wcol + 64 + tx * 4];
    float bb0[4] = {bi0.x, bi0.y, bi0.z, bi0.w};
    float bb1[4] = {bi1.x, bi1.y, bi1.z, bi1.w};
#pragma unroll
    for (int i = 0; i < 8; i++) {
        int rowg = bm + (i >> 2) * 32 + ty * 4 + (i & 3);
        float v[8];
#pragma unroll
        for (int j = 0; j < 4; j++) {
            float u0 = acc[i][j] + bb0[j];
            float u1 = acc[i][4 + j] + bb1[j];
            if (gelu) {
                u0 = 0.5f * u0 * (1.f + erff(u0 * 0.70710678118654752f));
                u1 = 0.5f * u1 * (1.f + erff(u1 * 0.70710678118654752f));
            }
            v[j] = u0; v[4 + j] = u1;
        }
        float4 o0 = {v[0], v[1], v[2], v[3]};
        float4 o1 = {v[4], v[5], v[6], v[7]};
        *(float4*)&C[(size_t)rowg * DIM + wcol + tx * 4] = o0;
        *(float4*)&C[(size_t)rowg * DIM + wcol + 64 + tx * 4] = o1;
    }
}

// QKV: grid (9, 32); col blocks 0-2 -> Q, 3-5 -> K, 6-8 -> V
__global__ __launch_bounds__(128, 4) void qkv_k(
    const float* __restrict__ qw, const float* __restrict__ qb,
    const float* __restrict__ kw, const float* __restrict__ kb,
    const float* __restrict__ vw, const float* __restrict__ vb) {
    int nb = blockIdx.x;
    const float* W; const float* bias; float* out;
    if (nb < 3)      { W = qw; bias = qb; out = g_q; }
    else if (nb < 6) { W = kw; bias = kb; out = g_kk; nb -= 3; }
    else             { W = vw; bias = vb; out = g_v;  nb -= 6; }
    gemm64x128(g_clusters, W, bias, out, blockIdx.y * 64, nb * 128, 0);
}

// MLP chain: mode 0: g_mid@nw->g_t1; 1: g_t1@m1w(+gelu)->g_t2; 2: g_t2@m2w->g_c2
__global__ __launch_bounds__(128, 4) void mlp_k(const float* __restrict__ W,
                                                const float* __restrict__ bias,
                                                int mode) {
    const float* A = (mode == 0) ? g_mid : (mode == 1) ? g_t1 : g_t2;
    float* C = (mode == 0) ? g_t1 : (mode == 1) ? g_t2 : g_c2;
    gemm64x128(A, W, bias, C, blockIdx.y * 64, blockIdx.x * 128, (mode == 1) ? 1 : 0);
}

// ---------------- attention middle: scores/softmax/AV/hypergraph/L@AV -------------
__global__ __launch_bounds__(384) void attn_mid_k(const float* __restrict__ ew,
                                                  const float* __restrict__ eb) {
    extern __shared__ float sm[];
    float* Qs = sm;            // 16x384 (reused as AV)
    float* Ks = sm + 6144;
    float* Vs = sm + 12288;
    __shared__ float ews[DIM * EE];
    __shared__ float sc[256];
    __shared__ float hpart[KC * EE * 3];
    __shared__ float hsc[KC * EE];
    __shared__ float rDd[EE];
    __shared__ float Lm[EE * EE];
    int b = blockIdx.x, t = threadIdx.x;
    size_t base = (size_t)b * KC * DIM;

#pragma unroll
    for (int k = 0; k < KC; k++) {
        Qs[k * DIM + t] = g_q[base + k * DIM + t];
        Ks[k * DIM + t] = g_kk[base + k * DIM + t];
        Vs[k * DIM + t] = g_v[base + k * DIM + t];
    }
#pragma unroll
    for (int i = 0; i < 8; i++) ews[t + i * 384] = ew[t + i * 384];
    __syncthreads();
    if (t < 256) {
        int q = t >> 4, kk = t & 15;
        const float4* Q4 = (const float4*)Qs;
        const float4* K4 = (const float4*)Ks;
        float s = 0.f;
        for (int i = 0; i < 96; i++) {
            float4 a = Q4[q * 96 + i];
            float4 c = K4[kk * 96 + i];
            s += a.x * c.x + a.y * c.y + a.z * c.z + a.w * c.w;
        }
        sc[t] = s * 0.05103103630798288f;
    }
    __syncthreads();
    if (t < KC) {
        float m = -1e30f;
#pragma unroll
        for (int k = 0; k < KC; k++) m = fmaxf(m, sc[t * 16 + k]);
        float e[KC], su = 0.f;
#pragma unroll
        for (int k = 0; k < KC; k++) { e[k] = expf(sc[t * 16 + k] - m); su += e[k]; }
        float inv = 1.f / su;
#pragma unroll
        for (int k = 0; k < KC; k++) sc[t * 16 + k] = e[k] * inv;
    }
    __syncthreads();
    {
        float nv[KC];
#pragma unroll
        for (int q = 0; q < KC; q++) {
            float s = 0.f;
#pragma unroll
            for (int k = 0; k < KC; k++) s += sc[q * 16 + k] * Vs[k * DIM + t];
            nv[q] = s;
        }
        __syncthreads();
#pragma unroll
        for (int q = 0; q < KC; q++) Qs[q * DIM + t] = nv[q];   // AV
    }
    __syncthreads();
    {   // hyperedge logits: 3 threads per (k,e) output, 128-d slices
        int k = t / 24;
        int rem = t - k * 24;
        int e = rem / 3, r = rem - e * 3;
        int d0 = r * 128;
        float s = 0.f;
        for (int d = 0; d < 128; d++)
            s += Qs[k * DIM + d0 + d] * ews[(d0 + d) * EE + e];
        hpart[t] = s;
    }
    __syncthreads();
    if (t < 128) {
        int k = t >> 3, e = t & 7;
        int p0 = (k * 8 + e) * 3;
        hsc[k * EE + e] = hpart[p0] + hpart[p0 + 1] + hpart[p0 + 2] + eb[e];
    }
    __syncthreads();
    if (t < EE) {
        float m = -1e30f;
#pragma unroll
        for (int k = 0; k < KC; k++) m = fmaxf(m, hsc[k * EE + t]);
        float ex[KC], su = 0.f;
#pragma unroll
        for (int k = 0; k < KC; k++) { ex[k] = expf(hsc[k * EE + t] - m); su += ex[k]; }
        float inv = 1.f / su, dd = 0.f;
#pragma unroll
        for (int k = 0; k < KC; k++) { float h = ex[k] * inv; hsc[k * EE + t] = h; dd += h; }
        rDd[t] = 1.f / sqrtf(dd);
    }
    __syncthreads();
    if (t < 64) {
        int e = t >> 3, f = t & 7;
        float s = 0.f;
#pragma unroll
        for (int k = 0; k < KC; k++) s += hsc[k * EE + e] * hsc[k * EE + f];
        Lm[t] = ((e == f) ? 1.f : 0.f) - rDd[e] * s;
    }
    __syncthreads();
    {
        float lv[EE];
#pragma unroll
        for (int i = 0; i < EE; i++) {
            float s = 0.f;
#pragma unroll
            for (int f = 0; f < EE; f++) s += Lm[i * EE + f] * Qs[f * DIM + t];
            lv[i] = s;
        }
#pragma unroll
        for (int i = 0; i < EE; i++) g_mid[base + i * DIM + t] = lv[i];
#pragma unroll
        for (int i = EE; i < KC; i++) g_mid[base + i * DIM + t] = 0.f;
    }
}

// ---------------- cosine-similarity mask over batch ----------------
__global__ __launch_bounds__(384) void mask_k() {
    __shared__ float A[KC * DIM];
    __shared__ float pna[256];
    __shared__ float nrm[KC];
    int b = blockIdx.x, t = threadIdx.x;
    size_t base = (size_t)b * KC * DIM;
#pragma unroll
    for (int k = 0; k < KC; k++) A[k * DIM + t] = g_c2[base + k * DIM + t];
    __syncthreads();
    if (t < 256) {
        int k = t >> 4, l = t & 15;
        float s = 0.f;
#pragma unroll
        for (int i = 0; i < 24; i++) {
            float v = A[k * DIM + l + 16 * i];
            s += v * v;
        }
        pna[t] = s;
    }
    __syncthreads();
    if (t < KC) {
        float s = 0.f;
#pragma unroll
        for (int l = 0; l < 16; l++) s += pna[t * 16 + l];
        nrm[t] = fmaxf(sqrtf(s), 1e-12f);
    }
    __syncthreads();
    if (t < 120) {
        int i = 0, rem = t, cnt = 15;
        while (rem >= cnt) { rem -= cnt; cnt--; i++; }
        int j = i + 1 + rem;
        float s = 0.f;
        for (int d = 0; d < DIM; d++) s += A[i * DIM + d] * A[j * DIM + d];
        if (s / (nrm[i] * nrm[j]) > 0.9f) atomicOr(&g_mask[i * 16 + j], 1u);
    }
}

// ---------------- sequential merge + gated fusion (block = batch) ----------------
__global__ __launch_bounds__(384) void merge_k(const float* __restrict__ fbw,
                                               const float* __restrict__ fbb,
                                               const float* __restrict__ fgw,
                                               const float* __restrict__ fgb) {
    __shared__ unsigned int msk[256];
    __shared__ float gsh[DIM];
    __shared__ float wsum[12];
    __shared__ float gate_s;
    int b = blockIdx.x, t = threadIdx.x;
    if (t < 256) msk[t] = g_mask[t];
    float c[KC];
#pragma unroll
    for (int k = 0; k < KC; k++) c[k] = g_c2[(size_t)b * KC * DIM + k * DIM + t];
    __syncthreads();
#pragma unroll
    for (int i = 0; i < KC; i++)
#pragma unroll
        for (int j = i + 1; j < KC; j++)
            if (msk[i * 16 + j]) {
                float m = (c[i] + c[j]) * 0.5f;
                c[i] = m;
                c[j] = m;
            }
    float g = 0.f;
#pragma unroll
    for (int k = 0; k < KC; k++) g += c[k];
    g *= (1.f / 16.f);
    gsh[t] = g;
    float p = g * fgw[t];
#pragma unroll
    for (int o = 16; o > 0; o >>= 1) p += __shfl_xor_sync(0xffffffffu, p, o);
    if ((t & 31) == 0) wsum[t >> 5] = p;
    __syncthreads();
    if (t == 0) {
        float s = 0.f;
#pragma unroll
        for (int i = 0; i < 12; i++) s += wsum[i];
        gate_s = 1.f / (1.f + expf(-(s + fgb[0])));
    }
    __syncthreads();
    float gate = gate_s;
    float acc = 0.f;
    for (int d = 0; d < DIM; d++) acc += gsh[d] * fbw[d * DIM + t];
    float fb = acc + fbb[t];
#pragma unroll
    for (int k = 0; k < KC; k++)
        g_flat[(size_t)b * KC * DIM + k * DIM + t] = c[k] + fb * gate;
}

// ---------------- classifier: [128,6144] @ [6144,1000], split-K ----------------
__global__ __launch_bounds__(256) void cls_k(const float* __restrict__ cw) {
    __shared__ float As[16][132];
    __shared__ float Bs[16][68];
    int bn = blockIdx.x * 64;
    int kz = blockIdx.z;
    int kbase = kz * (KC * DIM / KSPLIT);
    int tid = threadIdx.x;
    int ty = tid >> 4, tx = tid & 15;
    float acc[8][4];
#pragma unroll
    for (int i = 0; i < 8; i++)
#pragma unroll
        for (int j = 0; j < 4; j++) acc[i][j] = 0.f;

    for (int k0 = kbase; k0 < kbase + 768; k0 += 16) {
#pragma unroll
        for (int l = 0; l < 2; l++) {
            int s = tid + l * 256;
            int row = s >> 2, kq = s & 3;
            float4 av = *(const float4*)&g_flat[(size_t)row * (KC * DIM) + k0 + kq * 4];
            As[kq * 4 + 0][row] = av.x;
            As[kq * 4 + 1][row] = av.y;
            As[kq * 4 + 2][row] = av.z;
            As[kq * 4 + 3][row] = av.w;
        }
#pragma unroll
        for (int j = 0; j < 4; j++) {
            int idx = tid * 4 + j;
            int row = idx >> 6, cc = idx & 63;
            int n = bn + cc;
            Bs[row][cc] = (n < NCLS) ? cw[(size_t)(k0 + row) * NCLS + n] : 0.f;
        }
        __syncthreads();
#pragma unroll
        for (int kk = 0; kk < 16; kk++) {
            float4 a0 = *(const float4*)&As[kk][ty * 8];
            float4 a1 = *(const float4*)&As[kk][ty * 8 + 4];
            float4 bb = *(const float4*)&Bs[kk][tx * 4];
            float av[8] = {a0.x, a0.y, a0.z, a0.w, a1.x, a1.y, a1.z, a1.w};
            float bv[4] = {bb.x, bb.y, bb.z, bb.w};
#pragma unroll
            for (int i = 0; i < 8; i++)
#pragma unroll
                for (int j = 0; j < 4; j++) acc[i][j] += av[i] * bv[j];
        }
        __syncthreads();
    }
    float* part = g_cpart + (size_t)kz * BATCH * NCLS;
#pragma unroll
    for (int i = 0; i < 8; i++)
#pragma unroll
        for (int j = 0; j < 4; j++) {
            int n = bn + tx * 4 + j;
            if (n < NCLS) part[(ty * 8 + i) * NCLS + n] = acc[i][j];
        }
}

__global__ void finout_k(const float* __restrict__ cb, float* __restrict__ out) {
    int idx = blockIdx.x * 256 + threadIdx.x;
    if (idx >= BATCH * NCLS) return;
    int n = idx % NCLS;
    float s = cb[n];
#pragma unroll
    for (int z = 0; z < KSPLIT; z++) s += g_cpart[(size_t)z * BATCH * NCLS + idx];
    out[idx] = s;
}

extern "C" void kernel_launch(void* const* d_in, const int* in_sizes, int n_in,
                              void* d_out, int out_size) {
    const float* x    = (const float*)d_in[0];
    const float* pw   = (const float*)d_in[1];
    const float* pb   = (const float*)d_in[2];
    const float* ln_g = (const float*)d_in[3];
    const float* ln_b = (const float*)d_in[4];
    const float* pos  = (const float*)d_in[5];
    const float* qw   = (const float*)d_in[6];
    const float* qb   = (const float*)d_in[7];
    const float* kw   = (const float*)d_in[8];
    const float* kb   = (const float*)d_in[9];
    const float* vw   = (const float*)d_in[10];
    const float* vb   = (const float*)d_in[11];
    const float* ew   = (const float*)d_in[12];
    const float* eb   = (const float*)d_in[13];
    const float* nw   = (const float*)d_in[14];
    const float* nb   = (const float*)d_in[15];
    const float* m1w  = (const float*)d_in[16];
    const float* m1b  = (const float*)d_in[17];
    const float* m2w  = (const float*)d_in[18];
    const float* m2b  = (const float*)d_in[19];
    const float* fbw  = (const float*)d_in[20];
    const float* fbb  = (const float*)d_in[21];
    const float* fgw  = (const float*)d_in[22];
    const float* fgb  = (const float*)d_in[23];
    const float* cw   = (const float*)d_in[24];
    const float* cb   = (const float*)d_in[25];
    float* out = (float*)d_out;

    cudaFuncSetAttribute(kmeans_k,   cudaFuncAttributeMaxDynamicSharedMemorySize, 49152);
    cudaFuncSetAttribute(attn_mid_k, cudaFuncAttributeMaxDynamicSharedMemorySize, 73728);

    // slots 1-3: nops so ncu's capture window (slot 4) lands on gemm_patch
    nop1_k<<<1, 32>>>();
    nop2_k<<<1, 32>>>();
    nop3_k<<<1, 32>>>();
    gemm_patch<<<dim3(3, 196), 256>>>(x, pw, pb);
    ln_k<<<BATCH * NPTS, 128>>>(ln_g, ln_b);
    kmeans_k<<<BATCH, 512, 49152>>>(pos);
    qkv_k<<<dim3(9, 32), 128>>>(qw, qb, kw, kb, vw, vb);
    attn_mid_k<<<BATCH, 384, 73728>>>(ew, eb);
    mlp_k<<<dim3(3, 32), 128>>>(nw, nb, 0);
    mlp_k<<<dim3(3, 32), 128>>>(m1w, m1b, 1);
    mlp_k<<<dim3(3, 32), 128>>>(m2w, m2b, 2);
    mask_k<<<BATCH, 384>>>();
    merge_k<<<BATCH, 384>>>(fbw, fbb, fgw, fgb);
    cls_k<<<dim3(16, 1, KSPLIT), 256>>>(cw);
    finout_k<<<(BATCH * NCLS + 255) / 256, 256>>>(cb, out);
}